// round 6
// baseline (speedup 1.0000x reference)
#include <cuda_runtime.h>

#define G_N 8192
#define IMG_W 512
#define IMG_H 512
#define TILE 16
#define TX_N (IMG_W / TILE)       // 32
#define TY_N (IMG_H / TILE)       // 32
#define N_TILES (TX_N * TY_N)     // 1024
#define NWORDS (G_N / 32)         // 256 bitmap words per tile
#define TPB 256
#define SORT_TPB 256
#define SORT_WPB 8                // warps per block (one gaussian per warp)

// Sorted (by depth) gaussian data, raster-ready layout. +1 slot for sentinel.
__device__ float4 d_A[G_N + 1];          // mx, my, 0.5*a, b
__device__ float4 d_B[G_N + 1];          // 0.5*c, sigma_max=ln(255*op), op, col.r
__device__ float2 d_C[G_N];              // col.g, col.b
__device__ float4 d_bbox[G_N];           // x0, y0, x1, y1
// Per-tile rank bitmaps: bit r set => sorted gaussian r overlaps the tile.
__device__ unsigned d_bits[N_TILES * NWORDS];   // 1 MB

// ---------------------------------------------------------------------------
// Kernel 1: clear bitmaps + stable rank-sort by depth + gather + bbox.
// One warp per gaussian; uint4 key loads. Composite key (depth_bits, index)
// reproduces argsort(stable=True) exactly (positive floats -> monotone bits).
// Each of the 1024 blocks also zeroes its 1KB slice of d_bits (binning runs
// after this kernel in stream order, so no extra sync needed).
// ---------------------------------------------------------------------------
__global__ __launch_bounds__(SORT_TPB) void sort_gather_kernel(
    const float* __restrict__ means2d,
    const float* __restrict__ conics,
    const float* __restrict__ colors,
    const float* __restrict__ opac,
    const float* __restrict__ depths)
{
    __shared__ uint4 s_k4[G_N / 4];   // 32 KB
    const int tid  = threadIdx.x;
    const int warp = tid >> 5, lane = tid & 31;

    // clear this block's slice of the bitmap (64 uint4 = 1KB per block)
    if (tid < NWORDS / 4)
        ((uint4*)d_bits)[blockIdx.x * (NWORDS / 4) + tid] = make_uint4(0u, 0u, 0u, 0u);
    if (blockIdx.x == 0 && tid == 0) {
        d_A[G_N] = make_float4(1e9f, 1e9f, 0.0f, 0.0f);   // sentinel: sg=0
        d_B[G_N] = make_float4(0.0f, -1.0f, 0.0f, 0.0f);  // smax=-1 -> never passes
    }

    const uint4* dbits = (const uint4*)depths;
    for (int j = tid; j < G_N / 4; j += SORT_TPB)
        s_k4[j] = dbits[j];
    __syncthreads();

    const int i = blockIdx.x * SORT_WPB + warp;
    const unsigned ki = ((const unsigned*)s_k4)[i];

    int cnt = 0;
#pragma unroll 8
    for (int t = 0; t < G_N / 128; ++t) {
        const int j4 = t * 32 + lane;
        const uint4 k = s_k4[j4];
        const int j = 4 * j4;
        cnt += (k.x < ki) || ((k.x == ki) && (j     < i));
        cnt += (k.y < ki) || ((k.y == ki) && (j + 1 < i));
        cnt += (k.z < ki) || ((k.z == ki) && (j + 2 < i));
        cnt += (k.w < ki) || ((k.w == ki) && (j + 3 < i));
    }
    const int r = __reduce_add_sync(0xffffffffu, cnt);

    if (lane == 0) {
        const float mx = means2d[2 * i];
        const float my = means2d[2 * i + 1];
        const float a  = conics[3 * i];
        const float b  = conics[3 * i + 1];
        const float c  = conics[3 * i + 2];
        const float op = opac[i];

        // alpha = op*exp(-sigma) >= 1/255  <=>  sigma <= ln(255*op) = smax
        const float smax = logf(op * 255.0f);
        const float det  = a * c - b * b;

        d_A[r] = make_float4(mx, my, 0.5f * a, b);
        d_B[r] = make_float4(0.5f * c, smax, op, colors[3 * i]);
        d_C[r] = make_float2(colors[3 * i + 1], colors[3 * i + 2]);

        float4 bb;
        if (smax > 0.0f && det > 0.0f) {
            const float rx = sqrtf(fmaxf(0.0f, 2.0f * smax * c / det)) * 1.001f + 0.01f;
            const float ry = sqrtf(fmaxf(0.0f, 2.0f * smax * a / det)) * 1.001f + 0.01f;
            bb = make_float4(mx - rx, my - ry, mx + rx, my + ry);
        } else {
            bb = make_float4(1e9f, 1e9f, -1e9f, -1e9f);
        }
        d_bbox[r] = bb;
    }
}

// ---------------------------------------------------------------------------
// Exact (conservative) ellipse-vs-rect: keep iff min over rect of
// sigma(p) = A2*dx^2 + b*dx*dy + C2*dy^2 is <= smax (+margin).
// ---------------------------------------------------------------------------
__device__ __forceinline__ bool ellipse_hits_rect(
    float mx, float my, float A2, float b, float C2, float smax,
    float X0, float X1, float Y0, float Y1)
{
    if (mx >= X0 && mx <= X1 && my >= Y0 && my <= Y1) return true;
    const float dx0 = X0 - mx, dx1 = X1 - mx;
    const float dy0 = Y0 - my, dy1 = Y1 - my;
    const float fy = __fdividef(-b, 2.0f * C2);
    const float fx = __fdividef(-b, 2.0f * A2);

    float q = 3.4e38f;
    {   const float y = fminf(fmaxf(fy * dx0, dy0), dy1);
        q = fminf(q, A2 * dx0 * dx0 + b * dx0 * y + C2 * y * y); }
    {   const float y = fminf(fmaxf(fy * dx1, dy0), dy1);
        q = fminf(q, A2 * dx1 * dx1 + b * dx1 * y + C2 * y * y); }
    {   const float x = fminf(fmaxf(fx * dy0, dx0), dx1);
        q = fminf(q, A2 * x * x + b * x * dy0 + C2 * dy0 * dy0); }
    {   const float x = fminf(fmaxf(fx * dy1, dx0), dx1);
        q = fminf(q, A2 * x * x + b * x * dy1 + C2 * dy1 * dy1); }
    return q <= smax + 1e-2f;    // conservative margin (over-keep only)
}

// ---------------------------------------------------------------------------
// Kernel 2: binning. 8 lanes per gaussian (4 gaussians/warp); lanes split the
// covered tile range. atomicOr is order-independent -> deterministic.
// ---------------------------------------------------------------------------
__global__ __launch_bounds__(TPB) void binning_kernel()
{
    const int r   = (blockIdx.x * (TPB / 32) + (threadIdx.x >> 5)) * 4
                  + ((threadIdx.x >> 3) & 3);
    const int sub = threadIdx.x & 7;

    const float4 bb = d_bbox[r];
    if (bb.x > bb.z) return;

    const int tx0 = max(0, __float2int_rd((bb.x - 0.5f) * (1.0f / 16.0f)));
    const int tx1 = min(TX_N - 1, __float2int_rd((bb.z - 0.5f) * (1.0f / 16.0f)));
    const int ty0 = max(0, __float2int_rd((bb.y - 0.5f) * (1.0f / 16.0f)));
    const int ty1 = min(TY_N - 1, __float2int_rd((bb.w - 0.5f) * (1.0f / 16.0f)));
    if (tx1 < tx0 || ty1 < ty0) return;

    const int W = tx1 - tx0 + 1;
    const int n = W * (ty1 - ty0 + 1);

    const float4 A = d_A[r];    // mx, my, a/2, b
    const float4 B = d_B[r];    // c/2, smax, op, col.r

    for (int t = sub; t < n; t += 8) {
        const int tx = tx0 + t % W;
        const int ty = ty0 + t / W;
        const float X0 = (float)(tx * TILE) + 0.5f;
        const float Y0 = (float)(ty * TILE) + 0.5f;
        if (ellipse_hits_rect(A.x, A.y, A.z, A.w, B.x, B.y,
                              X0, X0 + (float)(TILE - 1),
                              Y0, Y0 + (float)(TILE - 1))) {
            const int tile = ty * TX_N + tx;
            atomicOr(&d_bits[tile * NWORDS + (r >> 5)], 1u << (r & 31));
        }
    }
}

// ---------------------------------------------------------------------------
// Kernel 3: raster. One 16x16 tile per block, 1 px/thread.
// Phase 1: bitmap -> compact uint16 rank list (ascending rank == depth
// order), padded to a multiple of 32 with a sentinel rank.
// Phase 2: batches of 32 ranks; fixed-count inner loop unrolled 4x with
// UNCONDITIONAL broadcast loads (enables ptxas load pipelining / MLP);
// exact early exit at T < 1e-4 checked block-wide per batch.
// ---------------------------------------------------------------------------
__global__ __launch_bounds__(TPB) void raster_kernel(float* __restrict__ out)
{
    const int tileX = blockIdx.x, tileY = blockIdx.y;
    const int tileI = tileY * TX_N + tileX;
    const int tid   = threadIdx.x;
    const int warp  = tid >> 5, lane = tid & 31;
    const float px  = (float)(tileX * TILE + (tid & (TILE - 1))) + 0.5f;
    const float py  = (float)(tileY * TILE + (tid >> 4)) + 0.5f;

    __shared__ unsigned short s_list[G_N + 32];   // worst case + sentinel pad
    __shared__ int s_wsum[8];
    __shared__ int s_cnt;

    // ---- Phase 1: build list ----
    const unsigned w = d_bits[tileI * NWORDS + tid];
    const int c = __popc(w);

    int incl = c;
#pragma unroll
    for (int o = 1; o < 32; o <<= 1) {
        const int v = __shfl_up_sync(0xffffffffu, incl, o);
        if (lane >= o) incl += v;
    }
    if (lane == 31) s_wsum[warp] = incl;
    __syncthreads();
    int base = 0;
#pragma unroll
    for (int k = 0; k < 8; ++k)
        if (k < warp) base += s_wsum[k];
    if (tid == 0) {
        int tot = 0;
#pragma unroll
        for (int k = 0; k < 8; ++k) tot += s_wsum[k];
        s_cnt = tot;
    }
    int ofs = base + incl - c;
    unsigned bits = w;
    const int rbase = tid << 5;
    while (bits) {
        const int rb = __ffs(bits) - 1;
        bits &= bits - 1;
        s_list[ofs++] = (unsigned short)(rbase + rb);
    }
    __syncthreads();
    const int cnt = s_cnt;
    if (tid < 32) s_list[cnt + tid] = (unsigned short)G_N;   // sentinel pad
    __syncthreads();

    // ---- Phase 2: composite ----
    float T = 1.0f;
    float aR = 0.0f, aG = 0.0f, aB = 0.0f;
    bool done = false;

    const int cnt_pad = (cnt + 31) & ~31;
#pragma unroll 1
    for (int j0 = 0; j0 < cnt_pad; j0 += 32) {
#pragma unroll 4
        for (int jj = 0; jj < 32; ++jj) {
            const int r = s_list[j0 + jj];
            const float4 A = d_A[r];       // broadcast; unconditional -> pipelined
            const float4 B = d_B[r];
            const float dx = px - A.x;
            const float dy = py - A.y;
            const float sg = fmaf(A.z * dx, dx,
                             fmaf(B.x * dy, dy, A.w * dx * dy));
            if (!done && sg >= 0.0f && sg <= B.y) {
                const float2 C = d_C[r];
                const float alpha = fminf(0.99f, B.z * __expf(-sg));
                const float wgt = alpha * T;
                aR += wgt * B.w; aG += wgt * C.x; aB += wgt * C.y;
                T *= (1.0f - alpha);
                done = (T < 1e-4f);
            }
        }
        if (__syncthreads_count(done ? 0 : 1) == 0) break;
    }

    float* o = out + ((size_t)(tileY * TILE + (tid >> 4)) * IMG_W
                      + (tileX * TILE + (tid & (TILE - 1)))) * 3;
    o[0] = aR;
    o[1] = aG;
    o[2] = aB;
}

// ---------------------------------------------------------------------------
extern "C" void kernel_launch(void* const* d_in, const int* in_sizes, int n_in,
                              void* d_out, int out_size)
{
    const float* means2d   = (const float*)d_in[0];
    const float* conics    = (const float*)d_in[1];
    const float* colors    = (const float*)d_in[2];
    const float* opacities = (const float*)d_in[3];
    const float* depths    = (const float*)d_in[4];
    float* out = (float*)d_out;

    sort_gather_kernel<<<G_N / SORT_WPB, SORT_TPB>>>(means2d, conics, colors, opacities, depths);
    binning_kernel<<<G_N / ((TPB / 32) * 4), TPB>>>();
    dim3 grid(TX_N, TY_N);
    raster_kernel<<<grid, TPB>>>(out);
}

// round 7
// speedup vs baseline: 1.2659x; 1.2659x over previous
#include <cuda_runtime.h>

#define G_N 8192
#define IMG_W 512
#define IMG_H 512
#define TILE 16
#define TX_N (IMG_W / TILE)       // 32
#define TY_N (IMG_H / TILE)       // 32
#define N_TILES (TX_N * TY_N)     // 1024
#define NWORDS (G_N / 32)         // 256 bitmap words per tile
#define TPB 256
#define SORT_TPB 256
#define SORT_WPB 8                // warps per block (one gaussian per warp)

// Sorted (by depth) gaussian data, raster-ready layout. +1 slot for sentinel.
__device__ float4 d_A[G_N + 1];          // mx, my, 0.5*a, b
__device__ float4 d_B[G_N + 1];          // 0.5*c, sigma_max=ln(255*op), op, col.r
__device__ float2 d_C[G_N];              // col.g, col.b
__device__ float4 d_bbox[G_N];           // x0, y0, x1, y1
// Per-tile rank bitmaps: bit r set => sorted gaussian r overlaps the tile.
__device__ unsigned d_bits[N_TILES * NWORDS];   // 1 MB

// ---------------------------------------------------------------------------
// Kernel 1: clear bitmaps + stable rank-sort by depth + gather + bbox.
// One warp per gaussian; uint2 key loads (2-phase LDS, conflict-free).
// Composite key (depth_bits, index) reproduces argsort(stable=True) exactly
// (positive floats -> monotone bits). Each of the 1024 blocks also zeroes its
// 1KB slice of d_bits (binning runs after in stream order).
// ---------------------------------------------------------------------------
__global__ __launch_bounds__(SORT_TPB) void sort_gather_kernel(
    const float* __restrict__ means2d,
    const float* __restrict__ conics,
    const float* __restrict__ colors,
    const float* __restrict__ opac,
    const float* __restrict__ depths)
{
    __shared__ uint2 s_bits2[G_N / 2];   // 32 KB
    const int tid  = threadIdx.x;
    const int warp = tid >> 5, lane = tid & 31;

    // clear this block's slice of the bitmap (64 uint4 = 1KB per block)
    if (tid < NWORDS / 4)
        ((uint4*)d_bits)[blockIdx.x * (NWORDS / 4) + tid] = make_uint4(0u, 0u, 0u, 0u);
    if (blockIdx.x == 0 && tid == 0) {
        d_A[G_N] = make_float4(1e9f, 1e9f, 0.0f, 0.0f);   // sentinel
        d_B[G_N] = make_float4(0.0f, -1.0f, 0.0f, 0.0f);  // smax=-1 -> never passes
    }

    const uint2* dbits = (const uint2*)depths;
    for (int j = tid; j < G_N / 2; j += SORT_TPB)
        s_bits2[j] = dbits[j];
    __syncthreads();

    const int i = blockIdx.x * SORT_WPB + warp;
    const unsigned ki = ((const unsigned*)s_bits2)[i];

    int cnt = 0;
#pragma unroll 8
    for (int t = 0; t < G_N / 64; ++t) {
        const int j2 = t * 32 + lane;
        const uint2 kj = s_bits2[j2];
        const int j = 2 * j2;
        cnt += (kj.x < ki) || ((kj.x == ki) && (j     < i));
        cnt += (kj.y < ki) || ((kj.y == ki) && (j + 1 < i));
    }
    const int r = __reduce_add_sync(0xffffffffu, cnt);

    if (lane == 0) {
        const float mx = means2d[2 * i];
        const float my = means2d[2 * i + 1];
        const float a  = conics[3 * i];
        const float b  = conics[3 * i + 1];
        const float c  = conics[3 * i + 2];
        const float op = opac[i];

        // alpha = op*exp(-sigma) >= 1/255  <=>  sigma <= ln(255*op) = smax
        const float smax = logf(op * 255.0f);
        const float det  = a * c - b * b;

        d_A[r] = make_float4(mx, my, 0.5f * a, b);
        d_B[r] = make_float4(0.5f * c, smax, op, colors[3 * i]);
        d_C[r] = make_float2(colors[3 * i + 1], colors[3 * i + 2]);

        float4 bb;
        if (smax > 0.0f && det > 0.0f) {
            const float rx = sqrtf(fmaxf(0.0f, 2.0f * smax * c / det)) * 1.001f + 0.01f;
            const float ry = sqrtf(fmaxf(0.0f, 2.0f * smax * a / det)) * 1.001f + 0.01f;
            bb = make_float4(mx - rx, my - ry, mx + rx, my + ry);
        } else {
            bb = make_float4(1e9f, 1e9f, -1e9f, -1e9f);
        }
        d_bbox[r] = bb;
    }
}

// ---------------------------------------------------------------------------
// Exact (conservative) ellipse-vs-rect: keep iff min over rect of
// sigma(p) = A2*dx^2 + b*dx*dy + C2*dy^2 is <= smax (+margin).
// ---------------------------------------------------------------------------
__device__ __forceinline__ bool ellipse_hits_rect(
    float mx, float my, float A2, float b, float C2, float smax,
    float X0, float X1, float Y0, float Y1)
{
    if (mx >= X0 && mx <= X1 && my >= Y0 && my <= Y1) return true;
    const float dx0 = X0 - mx, dx1 = X1 - mx;
    const float dy0 = Y0 - my, dy1 = Y1 - my;
    const float fy = __fdividef(-b, 2.0f * C2);
    const float fx = __fdividef(-b, 2.0f * A2);

    float q = 3.4e38f;
    {   const float y = fminf(fmaxf(fy * dx0, dy0), dy1);
        q = fminf(q, A2 * dx0 * dx0 + b * dx0 * y + C2 * y * y); }
    {   const float y = fminf(fmaxf(fy * dx1, dy0), dy1);
        q = fminf(q, A2 * dx1 * dx1 + b * dx1 * y + C2 * y * y); }
    {   const float x = fminf(fmaxf(fx * dy0, dx0), dx1);
        q = fminf(q, A2 * x * x + b * x * dy0 + C2 * dy0 * dy0); }
    {   const float x = fminf(fmaxf(fx * dy1, dx0), dx1);
        q = fminf(q, A2 * x * x + b * x * dy1 + C2 * dy1 * dy1); }
    return q <= smax + 1e-2f;    // conservative margin (over-keep only)
}

// ---------------------------------------------------------------------------
// Kernel 2: binning. 8 lanes per gaussian (4 gaussians/warp); lanes split the
// covered tile range. atomicOr is order-independent -> deterministic.
// ---------------------------------------------------------------------------
__global__ __launch_bounds__(TPB) void binning_kernel()
{
    const int r   = (blockIdx.x * (TPB / 32) + (threadIdx.x >> 5)) * 4
                  + ((threadIdx.x >> 3) & 3);
    const int sub = threadIdx.x & 7;

    const float4 bb = d_bbox[r];
    if (bb.x > bb.z) return;

    const int tx0 = max(0, __float2int_rd((bb.x - 0.5f) * (1.0f / 16.0f)));
    const int tx1 = min(TX_N - 1, __float2int_rd((bb.z - 0.5f) * (1.0f / 16.0f)));
    const int ty0 = max(0, __float2int_rd((bb.y - 0.5f) * (1.0f / 16.0f)));
    const int ty1 = min(TY_N - 1, __float2int_rd((bb.w - 0.5f) * (1.0f / 16.0f)));
    if (tx1 < tx0 || ty1 < ty0) return;

    const int W = tx1 - tx0 + 1;
    const int n = W * (ty1 - ty0 + 1);

    const float4 A = d_A[r];    // mx, my, a/2, b
    const float4 B = d_B[r];    // c/2, smax, op, col.r

    for (int t = sub; t < n; t += 8) {
        const int tx = tx0 + t % W;
        const int ty = ty0 + t / W;
        const float X0 = (float)(tx * TILE) + 0.5f;
        const float Y0 = (float)(ty * TILE) + 0.5f;
        if (ellipse_hits_rect(A.x, A.y, A.z, A.w, B.x, B.y,
                              X0, X0 + (float)(TILE - 1),
                              Y0, Y0 + (float)(TILE - 1))) {
            const int tile = ty * TX_N + tx;
            atomicOr(&d_bits[tile * NWORDS + (r >> 5)], 1u << (r & 31));
        }
    }
}

// ---------------------------------------------------------------------------
// Kernel 3: raster. One 16x16 tile per block, 1 px/thread.
// Phase 1: bitmap -> compact uint16 rank list (ascending rank == depth order),
// sentinel-padded so next-rank loads are always safe.
// Phase 2: R5-style guarded composite loop + 1-deep register prefetch of the
// next rank's A/B (hides part of the LDS->LDG dependent latency).
// Exact early exit at T < 1e-4 checked block-wide every 32 entries.
// ---------------------------------------------------------------------------
__global__ __launch_bounds__(TPB) void raster_kernel(float* __restrict__ out)
{
    const int tileX = blockIdx.x, tileY = blockIdx.y;
    const int tileI = tileY * TX_N + tileX;
    const int tid   = threadIdx.x;
    const int warp  = tid >> 5, lane = tid & 31;
    const float px  = (float)(tileX * TILE + (tid & (TILE - 1))) + 0.5f;
    const float py  = (float)(tileY * TILE + (tid >> 4)) + 0.5f;

    __shared__ unsigned short s_list[G_N + 33];   // worst case + sentinel pad
    __shared__ int s_wsum[8];
    __shared__ int s_cnt;

    // ---- Phase 1: build list ----
    const unsigned w = d_bits[tileI * NWORDS + tid];
    const int c = __popc(w);

    int incl = c;
#pragma unroll
    for (int o = 1; o < 32; o <<= 1) {
        const int v = __shfl_up_sync(0xffffffffu, incl, o);
        if (lane >= o) incl += v;
    }
    if (lane == 31) s_wsum[warp] = incl;
    __syncthreads();
    int base = 0;
#pragma unroll
    for (int k = 0; k < 8; ++k)
        if (k < warp) base += s_wsum[k];
    if (tid == 0) {
        int tot = 0;
#pragma unroll
        for (int k = 0; k < 8; ++k) tot += s_wsum[k];
        s_cnt = tot;
    }
    int ofs = base + incl - c;
    unsigned bits = w;
    const int rbase = tid << 5;
    while (bits) {
        const int rb = __ffs(bits) - 1;
        bits &= bits - 1;
        s_list[ofs++] = (unsigned short)(rbase + rb);
    }
    __syncthreads();
    const int cnt = s_cnt;
    if (tid < 33) s_list[cnt + tid] = (unsigned short)G_N;   // sentinel pad
    __syncthreads();

    // ---- Phase 2: composite ----
    float T = 1.0f;
    float aR = 0.0f, aG = 0.0f, aB = 0.0f;
    bool done = false;

    int rcur = s_list[0];
    float4 A = d_A[rcur];      // broadcast loads (same addr per warp)
    float4 B = d_B[rcur];

#pragma unroll 1
    for (int j = 0; j < cnt; ++j) {
        const float4 Ac = A;
        const float4 Bc = B;
        const int rc = rcur;
        rcur = s_list[j + 1];  // sentinel-safe
        A = d_A[rcur];         // prefetch next (unconditional)
        B = d_B[rcur];

        if (!done) {
            const float dx = px - Ac.x;
            const float dy = py - Ac.y;
            const float sg = fmaf(Ac.z * dx, dx,
                             fmaf(Bc.x * dy, dy, Ac.w * dx * dy));
            if (sg >= 0.0f && sg <= Bc.y) {
                const float2 C = __ldg(&d_C[rc]);
                const float alpha = fminf(0.99f, Bc.z * __expf(-sg));
                const float wgt = alpha * T;
                aR += wgt * Bc.w; aG += wgt * C.x; aB += wgt * C.y;
                T *= (1.0f - alpha);
                done = (T < 1e-4f);
            }
        }
        if (((j + 1) & 31) == 0) {
            if (__syncthreads_count(done ? 0 : 1) == 0) break;
        }
    }

    float* o = out + ((size_t)(tileY * TILE + (tid >> 4)) * IMG_W
                      + (tileX * TILE + (tid & (TILE - 1)))) * 3;
    o[0] = aR;
    o[1] = aG;
    o[2] = aB;
}

// ---------------------------------------------------------------------------
extern "C" void kernel_launch(void* const* d_in, const int* in_sizes, int n_in,
                              void* d_out, int out_size)
{
    const float* means2d   = (const float*)d_in[0];
    const float* conics    = (const float*)d_in[1];
    const float* colors    = (const float*)d_in[2];
    const float* opacities = (const float*)d_in[3];
    const float* depths    = (const float*)d_in[4];
    float* out = (float*)d_out;

    sort_gather_kernel<<<G_N / SORT_WPB, SORT_TPB>>>(means2d, conics, colors, opacities, depths);
    binning_kernel<<<G_N / ((TPB / 32) * 4), TPB>>>();
    dim3 grid(TX_N, TY_N);
    raster_kernel<<<grid, TPB>>>(out);
}

// round 8
// speedup vs baseline: 1.5759x; 1.2449x over previous
#include <cuda_runtime.h>

#define G_N 8192
#define IMG_W 512
#define IMG_H 512
#define TILE 16
#define TX_N (IMG_W / TILE)       // 32
#define TY_N (IMG_H / TILE)       // 32
#define N_TILES (TX_N * TY_N)     // 1024
#define NWORDS (G_N / 32)         // 256 bitmap words per tile
#define TPB 256
#define SORT_TPB 256
#define SORT_WPB 8                // warps per block (one gaussian per warp)

// Sorted (by depth) gaussian data, raster-ready layout.
__device__ float4 d_A[G_N];              // mx, my, 0.5*a, b
__device__ float4 d_B[G_N];              // 0.5*c, sigma_max=ln(255*op), op, col.r
__device__ float2 d_C[G_N];              // col.g, col.b
__device__ float4 d_bbox[G_N];           // x0, y0, x1, y1
// Per-tile rank bitmaps: bit r set => sorted gaussian r overlaps the tile.
__device__ unsigned d_bits[N_TILES * NWORDS];   // 1 MB

// ---------------------------------------------------------------------------
// Kernel 1: clear bitmaps + stable rank-sort by depth + gather + bbox.
// One warp per gaussian; uint2 key loads. Split-loop comparator:
//   rank = #{j<i: kj<=ki} + #{j>=i: kj<ki}
// (exactly reproduces argsort(stable=True): positive floats -> monotone bits,
//  composite tie-break on index). i is warp-uniform -> no divergence.
// Each of the 1024 blocks also zeroes its 1KB slice of d_bits.
// ---------------------------------------------------------------------------
__global__ __launch_bounds__(SORT_TPB) void sort_gather_kernel(
    const float* __restrict__ means2d,
    const float* __restrict__ conics,
    const float* __restrict__ colors,
    const float* __restrict__ opac,
    const float* __restrict__ depths)
{
    __shared__ uint2 s_bits2[G_N / 2];   // 32 KB
    const int tid  = threadIdx.x;
    const int warp = tid >> 5, lane = tid & 31;

    // clear this block's slice of the bitmap (64 uint4 = 1KB per block)
    if (tid < NWORDS / 4)
        ((uint4*)d_bits)[blockIdx.x * (NWORDS / 4) + tid] = make_uint4(0u, 0u, 0u, 0u);

    const uint2* dbits = (const uint2*)depths;
    for (int j = tid; j < G_N / 2; j += SORT_TPB)
        s_bits2[j] = dbits[j];
    __syncthreads();

    const int i = blockIdx.x * SORT_WPB + warp;
    const unsigned ki = ((const unsigned*)s_bits2)[i];

    // iteration t covers elements j in [64t, 64t+63]
    const int tb = i >> 6;         // the single boundary iteration
    int cnt = 0;

#pragma unroll 4
    for (int t = 0; t < tb; ++t) {                 // all j < i: count kj <= ki
        const uint2 kj = s_bits2[t * 32 + lane];
        cnt += (kj.x <= ki);
        cnt += (kj.y <= ki);
    }
    {   // boundary iteration: full composite comparator
        const int j2 = tb * 32 + lane;
        const uint2 kj = s_bits2[j2];
        const int j = 2 * j2;
        cnt += (kj.x < ki) || ((kj.x == ki) && (j     < i));
        cnt += (kj.y < ki) || ((kj.y == ki) && (j + 1 < i));
    }
#pragma unroll 4
    for (int t = tb + 1; t < G_N / 64; ++t) {      // all j >= i: count kj < ki
        const uint2 kj = s_bits2[t * 32 + lane];
        cnt += (kj.x < ki);
        cnt += (kj.y < ki);
    }
    const int r = __reduce_add_sync(0xffffffffu, cnt);

    if (lane == 0) {
        const float mx = means2d[2 * i];
        const float my = means2d[2 * i + 1];
        const float a  = conics[3 * i];
        const float b  = conics[3 * i + 1];
        const float c  = conics[3 * i + 2];
        const float op = opac[i];

        // alpha = op*exp(-sigma) >= 1/255  <=>  sigma <= ln(255*op) = smax
        const float smax = logf(op * 255.0f);
        const float det  = a * c - b * b;

        d_A[r] = make_float4(mx, my, 0.5f * a, b);
        d_B[r] = make_float4(0.5f * c, smax, op, colors[3 * i]);
        d_C[r] = make_float2(colors[3 * i + 1], colors[3 * i + 2]);

        float4 bb;
        if (smax > 0.0f && det > 0.0f) {
            const float rx = sqrtf(fmaxf(0.0f, 2.0f * smax * c / det)) * 1.001f + 0.01f;
            const float ry = sqrtf(fmaxf(0.0f, 2.0f * smax * a / det)) * 1.001f + 0.01f;
            bb = make_float4(mx - rx, my - ry, mx + rx, my + ry);
        } else {
            bb = make_float4(1e9f, 1e9f, -1e9f, -1e9f);
        }
        d_bbox[r] = bb;
    }
}

// ---------------------------------------------------------------------------
// Exact (conservative) ellipse-vs-rect: keep iff min over rect of
// sigma(p) = A2*dx^2 + b*dx*dy + C2*dy^2 is <= smax (+margin).
// ---------------------------------------------------------------------------
__device__ __forceinline__ bool ellipse_hits_rect(
    float mx, float my, float A2, float b, float C2, float smax,
    float X0, float X1, float Y0, float Y1)
{
    if (mx >= X0 && mx <= X1 && my >= Y0 && my <= Y1) return true;
    const float dx0 = X0 - mx, dx1 = X1 - mx;
    const float dy0 = Y0 - my, dy1 = Y1 - my;
    const float fy = __fdividef(-b, 2.0f * C2);
    const float fx = __fdividef(-b, 2.0f * A2);

    float q = 3.4e38f;
    {   const float y = fminf(fmaxf(fy * dx0, dy0), dy1);
        q = fminf(q, A2 * dx0 * dx0 + b * dx0 * y + C2 * y * y); }
    {   const float y = fminf(fmaxf(fy * dx1, dy0), dy1);
        q = fminf(q, A2 * dx1 * dx1 + b * dx1 * y + C2 * y * y); }
    {   const float x = fminf(fmaxf(fx * dy0, dx0), dx1);
        q = fminf(q, A2 * x * x + b * x * dy0 + C2 * dy0 * dy0); }
    {   const float x = fminf(fmaxf(fx * dy1, dx0), dx1);
        q = fminf(q, A2 * x * x + b * x * dy1 + C2 * dy1 * dy1); }
    return q <= smax + 1e-2f;    // conservative margin (over-keep only)
}

// ---------------------------------------------------------------------------
// Kernel 2: binning. 8 lanes per gaussian (4 gaussians/warp); lanes split the
// covered tile range. atomicOr is order-independent -> deterministic.
// ---------------------------------------------------------------------------
__global__ __launch_bounds__(TPB) void binning_kernel()
{
    const int r   = (blockIdx.x * (TPB / 32) + (threadIdx.x >> 5)) * 4
                  + ((threadIdx.x >> 3) & 3);
    const int sub = threadIdx.x & 7;

    const float4 bb = d_bbox[r];
    if (bb.x > bb.z) return;

    const int tx0 = max(0, __float2int_rd((bb.x - 0.5f) * (1.0f / 16.0f)));
    const int tx1 = min(TX_N - 1, __float2int_rd((bb.z - 0.5f) * (1.0f / 16.0f)));
    const int ty0 = max(0, __float2int_rd((bb.y - 0.5f) * (1.0f / 16.0f)));
    const int ty1 = min(TY_N - 1, __float2int_rd((bb.w - 0.5f) * (1.0f / 16.0f)));
    if (tx1 < tx0 || ty1 < ty0) return;

    const int W = tx1 - tx0 + 1;
    const int n = W * (ty1 - ty0 + 1);

    const float4 A = d_A[r];    // mx, my, a/2, b
    const float4 B = d_B[r];    // c/2, smax, op, col.r

    for (int t = sub; t < n; t += 8) {
        const int tx = tx0 + t % W;
        const int ty = ty0 + t / W;
        const float X0 = (float)(tx * TILE) + 0.5f;
        const float Y0 = (float)(ty * TILE) + 0.5f;
        if (ellipse_hits_rect(A.x, A.y, A.z, A.w, B.x, B.y,
                              X0, X0 + (float)(TILE - 1),
                              Y0, Y0 + (float)(TILE - 1))) {
            const int tile = ty * TX_N + tx;
            atomicOr(&d_bits[tile * NWORDS + (r >> 5)], 1u << (r & 31));
        }
    }
}

// ---------------------------------------------------------------------------
// Kernel 3: raster. One 16x16 tile per block, 1 px/thread.
// Phase 1: bitmap -> compact uint16 rank list (ascending rank == depth order).
// Phase 2: guarded composite loop; NO barriers (list is read-only) --
// each warp walks independently and exits via __all_sync as soon as all its
// 32 pixels reach T < 1e-4 (exact: later weights are exactly zero).
// ---------------------------------------------------------------------------
__global__ __launch_bounds__(TPB) void raster_kernel(float* __restrict__ out)
{
    const int tileX = blockIdx.x, tileY = blockIdx.y;
    const int tileI = tileY * TX_N + tileX;
    const int tid   = threadIdx.x;
    const int warp  = tid >> 5, lane = tid & 31;
    const float px  = (float)(tileX * TILE + (tid & (TILE - 1))) + 0.5f;
    const float py  = (float)(tileY * TILE + (tid >> 4)) + 0.5f;

    __shared__ unsigned short s_list[G_N];   // worst case all ranks
    __shared__ int s_wsum[8];
    __shared__ int s_cnt;

    // ---- Phase 1: build list ----
    const unsigned w = d_bits[tileI * NWORDS + tid];
    const int c = __popc(w);

    int incl = c;
#pragma unroll
    for (int o = 1; o < 32; o <<= 1) {
        const int v = __shfl_up_sync(0xffffffffu, incl, o);
        if (lane >= o) incl += v;
    }
    if (lane == 31) s_wsum[warp] = incl;
    __syncthreads();
    int base = 0;
#pragma unroll
    for (int k = 0; k < 8; ++k)
        if (k < warp) base += s_wsum[k];
    if (tid == 0) {
        int tot = 0;
#pragma unroll
        for (int k = 0; k < 8; ++k) tot += s_wsum[k];
        s_cnt = tot;
    }
    int ofs = base + incl - c;
    unsigned bits = w;
    const int rbase = tid << 5;
    while (bits) {
        const int rb = __ffs(bits) - 1;
        bits &= bits - 1;
        s_list[ofs++] = (unsigned short)(rbase + rb);
    }
    __syncthreads();
    const int cnt = s_cnt;

    // ---- Phase 2: composite (warp-independent, barrier-free) ----
    float T = 1.0f;
    float aR = 0.0f, aG = 0.0f, aB = 0.0f;
    bool done = false;

#pragma unroll 1
    for (int j = 0; j < cnt; ++j) {
        if (!done) {
            const int r = s_list[j];
            const float4 A = __ldg(&d_A[r]);   // broadcast (same addr per warp)
            const float4 B = __ldg(&d_B[r]);
            const float dx = px - A.x;
            const float dy = py - A.y;
            const float sg = fmaf(A.z * dx, dx,
                             fmaf(B.x * dy, dy, A.w * dx * dy));
            if (sg >= 0.0f && sg <= B.y) {
                const float2 C = __ldg(&d_C[r]);
                const float alpha = fminf(0.99f, B.z * __expf(-sg));
                const float wgt = alpha * T;
                aR += wgt * B.w; aG += wgt * C.x; aB += wgt * C.y;
                T *= (1.0f - alpha);
                done = (T < 1e-4f);
            }
        }
        if (__all_sync(0xffffffffu, done)) break;
    }

    float* o = out + ((size_t)(tileY * TILE + (tid >> 4)) * IMG_W
                      + (tileX * TILE + (tid & (TILE - 1)))) * 3;
    o[0] = aR;
    o[1] = aG;
    o[2] = aB;
}

// ---------------------------------------------------------------------------
extern "C" void kernel_launch(void* const* d_in, const int* in_sizes, int n_in,
                              void* d_out, int out_size)
{
    const float* means2d   = (const float*)d_in[0];
    const float* conics    = (const float*)d_in[1];
    const float* colors    = (const float*)d_in[2];
    const float* opacities = (const float*)d_in[3];
    const float* depths    = (const float*)d_in[4];
    float* out = (float*)d_out;

    sort_gather_kernel<<<G_N / SORT_WPB, SORT_TPB>>>(means2d, conics, colors, opacities, depths);
    binning_kernel<<<G_N / ((TPB / 32) * 4), TPB>>>();
    dim3 grid(TX_N, TY_N);
    raster_kernel<<<grid, TPB>>>(out);
}

// round 9
// speedup vs baseline: 1.6201x; 1.0280x over previous
#include <cuda_runtime.h>

#define G_N 8192
#define IMG_W 512
#define IMG_H 512
#define TILE 16
#define TX_N (IMG_W / TILE)       // 32
#define TY_N (IMG_H / TILE)       // 32
#define N_TILES (TX_N * TY_N)     // 1024
#define NWORDS (G_N / 32)         // 256 bitmap words per tile
#define TPB 256
#define SORT_TPB 256
#define SORT_WPB 8                // warps per block
#define SORT_GPW 4                // gaussians ranked per warp
#define SORT_BLOCKS (G_N / (SORT_WPB * SORT_GPW))   // 256

// Sorted (by depth) gaussian data, raster-ready layout.
__device__ float4 d_A[G_N];              // mx, my, 0.5*a, b
__device__ float4 d_B[G_N];              // 0.5*c, sigma_max=ln(255*op), op, col.r
__device__ float2 d_C[G_N];              // col.g, col.b
__device__ float4 d_bbox[G_N];           // x0, y0, x1, y1
// Per-tile rank bitmaps: bit r set => sorted gaussian r overlaps the tile.
__device__ unsigned d_bits[N_TILES * NWORDS];   // 1 MB

// ---------------------------------------------------------------------------
// Kernel 1: clear bitmaps + stable rank-sort by depth + gather + bbox.
// 4 gaussians per warp sharing each loaded key pair (amortizes LDS + the
// 32KB-per-block key prologue 4x vs one-gaussian-per-warp). The 4 gaussians
// i0..i0+3 are 4-aligned -> same boundary block tb = i0>>6, so the exact
// split comparator applies to all four:
//   j<i: count kj<=ki ; j>i: count kj<ki ; t==tb: full composite.
// Reproduces argsort(stable=True) exactly (positive floats -> monotone bits).
// ---------------------------------------------------------------------------
__global__ __launch_bounds__(SORT_TPB) void sort_gather_kernel(
    const float* __restrict__ means2d,
    const float* __restrict__ conics,
    const float* __restrict__ colors,
    const float* __restrict__ opac,
    const float* __restrict__ depths)
{
    __shared__ uint2 s_k[G_N / 2];   // 32 KB
    const int tid  = threadIdx.x;
    const int warp = tid >> 5, lane = tid & 31;

    // clear this block's slice of the bitmap (256 uint4 = 4KB per block)
    ((uint4*)d_bits)[blockIdx.x * SORT_TPB + tid] = make_uint4(0u, 0u, 0u, 0u);

    const uint2* dbits = (const uint2*)depths;
    for (int j = tid; j < G_N / 2; j += SORT_TPB)
        s_k[j] = dbits[j];
    __syncthreads();

    const int i0 = (blockIdx.x * SORT_WPB + warp) * SORT_GPW;
    const unsigned* keys = (const unsigned*)s_k;
    const unsigned ki0 = keys[i0];
    const unsigned ki1 = keys[i0 + 1];
    const unsigned ki2 = keys[i0 + 2];
    const unsigned ki3 = keys[i0 + 3];
    const int tb = i0 >> 6;          // boundary iteration (same for all 4)

    int c0 = 0, c1 = 0, c2 = 0, c3 = 0;

#pragma unroll 4
    for (int t = 0; t < tb; ++t) {                 // j < i : kj <= ki
        const uint2 kj = s_k[t * 32 + lane];
        c0 += (kj.x <= ki0); c0 += (kj.y <= ki0);
        c1 += (kj.x <= ki1); c1 += (kj.y <= ki1);
        c2 += (kj.x <= ki2); c2 += (kj.y <= ki2);
        c3 += (kj.x <= ki3); c3 += (kj.y <= ki3);
    }
    {   // boundary iteration: full composite comparator
        const int j2 = tb * 32 + lane;
        const uint2 kj = s_k[j2];
        const int j = 2 * j2;
        c0 += (kj.x < ki0) || ((kj.x == ki0) && (j     < i0));
        c0 += (kj.y < ki0) || ((kj.y == ki0) && (j + 1 < i0));
        c1 += (kj.x < ki1) || ((kj.x == ki1) && (j     < i0 + 1));
        c1 += (kj.y < ki1) || ((kj.y == ki1) && (j + 1 < i0 + 1));
        c2 += (kj.x < ki2) || ((kj.x == ki2) && (j     < i0 + 2));
        c2 += (kj.y < ki2) || ((kj.y == ki2) && (j + 1 < i0 + 2));
        c3 += (kj.x < ki3) || ((kj.x == ki3) && (j     < i0 + 3));
        c3 += (kj.y < ki3) || ((kj.y == ki3) && (j + 1 < i0 + 3));
    }
#pragma unroll 4
    for (int t = tb + 1; t < G_N / 64; ++t) {      // j > i : kj < ki
        const uint2 kj = s_k[t * 32 + lane];
        c0 += (kj.x < ki0); c0 += (kj.y < ki0);
        c1 += (kj.x < ki1); c1 += (kj.y < ki1);
        c2 += (kj.x < ki2); c2 += (kj.y < ki2);
        c3 += (kj.x < ki3); c3 += (kj.y < ki3);
    }

    const int r0 = __reduce_add_sync(0xffffffffu, c0);
    const int r1 = __reduce_add_sync(0xffffffffu, c1);
    const int r2 = __reduce_add_sync(0xffffffffu, c2);
    const int r3 = __reduce_add_sync(0xffffffffu, c3);

    if (lane < SORT_GPW) {
        const int i = i0 + lane;
        const int r = (lane == 0) ? r0 : (lane == 1) ? r1 : (lane == 2) ? r2 : r3;

        const float mx = means2d[2 * i];
        const float my = means2d[2 * i + 1];
        const float a  = conics[3 * i];
        const float b  = conics[3 * i + 1];
        const float c  = conics[3 * i + 2];
        const float op = opac[i];

        // alpha = op*exp(-sigma) >= 1/255  <=>  sigma <= ln(255*op) = smax
        const float smax = logf(op * 255.0f);
        const float det  = a * c - b * b;

        d_A[r] = make_float4(mx, my, 0.5f * a, b);
        d_B[r] = make_float4(0.5f * c, smax, op, colors[3 * i]);
        d_C[r] = make_float2(colors[3 * i + 1], colors[3 * i + 2]);

        float4 bb;
        if (smax > 0.0f && det > 0.0f) {
            const float rx = sqrtf(fmaxf(0.0f, 2.0f * smax * c / det)) * 1.001f + 0.01f;
            const float ry = sqrtf(fmaxf(0.0f, 2.0f * smax * a / det)) * 1.001f + 0.01f;
            bb = make_float4(mx - rx, my - ry, mx + rx, my + ry);
        } else {
            bb = make_float4(1e9f, 1e9f, -1e9f, -1e9f);
        }
        d_bbox[r] = bb;
    }
}

// ---------------------------------------------------------------------------
// Exact (conservative) ellipse-vs-rect: keep iff min over rect of
// sigma(p) = A2*dx^2 + b*dx*dy + C2*dy^2 is <= smax (+margin).
// ---------------------------------------------------------------------------
__device__ __forceinline__ bool ellipse_hits_rect(
    float mx, float my, float A2, float b, float C2, float smax,
    float X0, float X1, float Y0, float Y1)
{
    if (mx >= X0 && mx <= X1 && my >= Y0 && my <= Y1) return true;
    const float dx0 = X0 - mx, dx1 = X1 - mx;
    const float dy0 = Y0 - my, dy1 = Y1 - my;
    const float fy = __fdividef(-b, 2.0f * C2);
    const float fx = __fdividef(-b, 2.0f * A2);

    float q = 3.4e38f;
    {   const float y = fminf(fmaxf(fy * dx0, dy0), dy1);
        q = fminf(q, A2 * dx0 * dx0 + b * dx0 * y + C2 * y * y); }
    {   const float y = fminf(fmaxf(fy * dx1, dy0), dy1);
        q = fminf(q, A2 * dx1 * dx1 + b * dx1 * y + C2 * y * y); }
    {   const float x = fminf(fmaxf(fx * dy0, dx0), dx1);
        q = fminf(q, A2 * x * x + b * x * dy0 + C2 * dy0 * dy0); }
    {   const float x = fminf(fmaxf(fx * dy1, dx0), dx1);
        q = fminf(q, A2 * x * x + b * x * dy1 + C2 * dy1 * dy1); }
    return q <= smax + 1e-2f;    // conservative margin (over-keep only)
}

// ---------------------------------------------------------------------------
// Kernel 2: binning. 8 lanes per gaussian (4 gaussians/warp); lanes split the
// covered tile range. atomicOr is order-independent -> deterministic.
// ---------------------------------------------------------------------------
__global__ __launch_bounds__(TPB) void binning_kernel()
{
    const int r   = (blockIdx.x * (TPB / 32) + (threadIdx.x >> 5)) * 4
                  + ((threadIdx.x >> 3) & 3);
    const int sub = threadIdx.x & 7;

    const float4 bb = d_bbox[r];
    if (bb.x > bb.z) return;

    const int tx0 = max(0, __float2int_rd((bb.x - 0.5f) * (1.0f / 16.0f)));
    const int tx1 = min(TX_N - 1, __float2int_rd((bb.z - 0.5f) * (1.0f / 16.0f)));
    const int ty0 = max(0, __float2int_rd((bb.y - 0.5f) * (1.0f / 16.0f)));
    const int ty1 = min(TY_N - 1, __float2int_rd((bb.w - 0.5f) * (1.0f / 16.0f)));
    if (tx1 < tx0 || ty1 < ty0) return;

    const int W = tx1 - tx0 + 1;
    const int n = W * (ty1 - ty0 + 1);

    const float4 A = d_A[r];    // mx, my, a/2, b
    const float4 B = d_B[r];    // c/2, smax, op, col.r

    for (int t = sub; t < n; t += 8) {
        const int tx = tx0 + t % W;
        const int ty = ty0 + t / W;
        const float X0 = (float)(tx * TILE) + 0.5f;
        const float Y0 = (float)(ty * TILE) + 0.5f;
        if (ellipse_hits_rect(A.x, A.y, A.z, A.w, B.x, B.y,
                              X0, X0 + (float)(TILE - 1),
                              Y0, Y0 + (float)(TILE - 1))) {
            const int tile = ty * TX_N + tx;
            atomicOr(&d_bits[tile * NWORDS + (r >> 5)], 1u << (r & 31));
        }
    }
}

// ---------------------------------------------------------------------------
// Kernel 3: raster. One 16x16 tile per block, 1 px/thread.
// Phase 1: bitmap -> compact uint16 rank list (ascending rank == depth order).
// Phase 2: guarded composite loop; NO barriers (list is read-only) --
// each warp walks independently and exits via __all_sync as soon as all its
// 32 pixels reach T < 1e-4 (exact: later weights are exactly zero).
// ---------------------------------------------------------------------------
__global__ __launch_bounds__(TPB) void raster_kernel(float* __restrict__ out)
{
    const int tileX = blockIdx.x, tileY = blockIdx.y;
    const int tileI = tileY * TX_N + tileX;
    const int tid   = threadIdx.x;
    const int warp  = tid >> 5, lane = tid & 31;
    const float px  = (float)(tileX * TILE + (tid & (TILE - 1))) + 0.5f;
    const float py  = (float)(tileY * TILE + (tid >> 4)) + 0.5f;

    __shared__ unsigned short s_list[G_N];   // worst case all ranks
    __shared__ int s_wsum[8];
    __shared__ int s_cnt;

    // ---- Phase 1: build list ----
    const unsigned w = d_bits[tileI * NWORDS + tid];
    const int c = __popc(w);

    int incl = c;
#pragma unroll
    for (int o = 1; o < 32; o <<= 1) {
        const int v = __shfl_up_sync(0xffffffffu, incl, o);
        if (lane >= o) incl += v;
    }
    if (lane == 31) s_wsum[warp] = incl;
    __syncthreads();
    int base = 0;
#pragma unroll
    for (int k = 0; k < 8; ++k)
        if (k < warp) base += s_wsum[k];
    if (tid == 0) {
        int tot = 0;
#pragma unroll
        for (int k = 0; k < 8; ++k) tot += s_wsum[k];
        s_cnt = tot;
    }
    int ofs = base + incl - c;
    unsigned bits = w;
    const int rbase = tid << 5;
    while (bits) {
        const int rb = __ffs(bits) - 1;
        bits &= bits - 1;
        s_list[ofs++] = (unsigned short)(rbase + rb);
    }
    __syncthreads();
    const int cnt = s_cnt;

    // ---- Phase 2: composite (warp-independent, barrier-free) ----
    float T = 1.0f;
    float aR = 0.0f, aG = 0.0f, aB = 0.0f;
    bool done = false;

#pragma unroll 1
    for (int j = 0; j < cnt; ++j) {
        if (!done) {
            const int r = s_list[j];
            const float4 A = __ldg(&d_A[r]);   // broadcast (same addr per warp)
            const float4 B = __ldg(&d_B[r]);
            const float dx = px - A.x;
            const float dy = py - A.y;
            const float sg = fmaf(A.z * dx, dx,
                             fmaf(B.x * dy, dy, A.w * dx * dy));
            if (sg >= 0.0f && sg <= B.y) {
                const float2 C = __ldg(&d_C[r]);
                const float alpha = fminf(0.99f, B.z * __expf(-sg));
                const float wgt = alpha * T;
                aR += wgt * B.w; aG += wgt * C.x; aB += wgt * C.y;
                T *= (1.0f - alpha);
                done = (T < 1e-4f);
            }
        }
        if (__all_sync(0xffffffffu, done)) break;
    }

    float* o = out + ((size_t)(tileY * TILE + (tid >> 4)) * IMG_W
                      + (tileX * TILE + (tid & (TILE - 1)))) * 3;
    o[0] = aR;
    o[1] = aG;
    o[2] = aB;
}

// ---------------------------------------------------------------------------
extern "C" void kernel_launch(void* const* d_in, const int* in_sizes, int n_in,
                              void* d_out, int out_size)
{
    const float* means2d   = (const float*)d_in[0];
    const float* conics    = (const float*)d_in[1];
    const float* colors    = (const float*)d_in[2];
    const float* opacities = (const float*)d_in[3];
    const float* depths    = (const float*)d_in[4];
    float* out = (float*)d_out;

    sort_gather_kernel<<<SORT_BLOCKS, SORT_TPB>>>(means2d, conics, colors, opacities, depths);
    binning_kernel<<<G_N / ((TPB / 32) * 4), TPB>>>();
    dim3 grid(TX_N, TY_N);
    raster_kernel<<<grid, TPB>>>(out);
}

// round 11
// speedup vs baseline: 1.7413x; 1.0748x over previous
#include <cuda_runtime.h>

#define G_N 8192
#define IMG_W 512
#define IMG_H 512
#define TILE 16
#define TX_N (IMG_W / TILE)       // 32
#define TY_N (IMG_H / TILE)       // 32
#define N_TILES (TX_N * TY_N)     // 1024
#define NWORDS (G_N / 32)         // 256 bitmap words per tile
#define TPB 256
#define CH 512                    // raster staging chunk (entries)
#define SORT_TPB 512
#define SORT_WPB (SORT_TPB / 32)  // 16 warps per block
#define SORT_GPW 2                // gaussians ranked per warp
#define SORT_BLOCKS (G_N / (SORT_WPB * SORT_GPW))   // 256
#define CLR_PER_BLK (N_TILES * NWORDS / 4 / SORT_BLOCKS)   // 256 uint4 per block

// Sorted (by depth) gaussian data, raster-ready layout.
__device__ float4 d_A[G_N];              // mx, my, 0.5*a, b
__device__ float4 d_B[G_N];              // 0.5*c, sigma_max=ln(255*op), op, col.r
__device__ float2 d_C[G_N];              // col.g, col.b
__device__ float4 d_bbox[G_N];           // x0, y0, x1, y1
// Per-tile rank bitmaps: bit r set => sorted gaussian r overlaps the tile.
__device__ unsigned d_bits[N_TILES * NWORDS];   // 1 MB

// ---------------------------------------------------------------------------
// Kernel 1: clear bitmaps + stable rank-sort by depth + gather + bbox.
// 512 threads (16 warps), 2 gaussians per warp. Split comparator (i0, i0+1
// share boundary block since i0 is even):
//   j<i: kj<=ki ; j>i: kj<ki ; boundary t==tb: full composite.
// Reproduces argsort(stable=True) exactly (positive floats -> monotone bits).
// ---------------------------------------------------------------------------
__global__ __launch_bounds__(SORT_TPB) void sort_gather_kernel(
    const float* __restrict__ means2d,
    const float* __restrict__ conics,
    const float* __restrict__ colors,
    const float* __restrict__ opac,
    const float* __restrict__ depths)
{
    __shared__ uint2 s_k[G_N / 2];   // 32 KB
    const int tid  = threadIdx.x;
    const int warp = tid >> 5, lane = tid & 31;

    // clear this block's slice of the bitmap (256 uint4 = 4KB per block)
    if (tid < CLR_PER_BLK)
        ((uint4*)d_bits)[blockIdx.x * CLR_PER_BLK + tid] = make_uint4(0u, 0u, 0u, 0u);

    const uint2* dbits = (const uint2*)depths;
    for (int j = tid; j < G_N / 2; j += SORT_TPB)
        s_k[j] = dbits[j];
    __syncthreads();

    const int i0 = (blockIdx.x * SORT_WPB + warp) * SORT_GPW;
    const unsigned* keys = (const unsigned*)s_k;
    const unsigned ki0 = keys[i0];
    const unsigned ki1 = keys[i0 + 1];
    const int tb = i0 >> 6;          // boundary iteration (same for both)

    int c0 = 0, c1 = 0;

#pragma unroll 4
    for (int t = 0; t < tb; ++t) {                 // j < i : kj <= ki
        const uint2 kj = s_k[t * 32 + lane];
        c0 += (kj.x <= ki0); c0 += (kj.y <= ki0);
        c1 += (kj.x <= ki1); c1 += (kj.y <= ki1);
    }
    {   // boundary iteration: full composite comparator
        const int j2 = tb * 32 + lane;
        const uint2 kj = s_k[j2];
        const int j = 2 * j2;
        c0 += (kj.x < ki0) || ((kj.x == ki0) && (j     < i0));
        c0 += (kj.y < ki0) || ((kj.y == ki0) && (j + 1 < i0));
        c1 += (kj.x < ki1) || ((kj.x == ki1) && (j     < i0 + 1));
        c1 += (kj.y < ki1) || ((kj.y == ki1) && (j + 1 < i0 + 1));
    }
#pragma unroll 4
    for (int t = tb + 1; t < G_N / 64; ++t) {      // j > i : kj < ki
        const uint2 kj = s_k[t * 32 + lane];
        c0 += (kj.x < ki0); c0 += (kj.y < ki0);
        c1 += (kj.x < ki1); c1 += (kj.y < ki1);
    }

    const int r0 = __reduce_add_sync(0xffffffffu, c0);
    const int r1 = __reduce_add_sync(0xffffffffu, c1);

    if (lane < SORT_GPW) {
        const int i = i0 + lane;
        const int r = (lane == 0) ? r0 : r1;

        const float mx = means2d[2 * i];
        const float my = means2d[2 * i + 1];
        const float a  = conics[3 * i];
        const float b  = conics[3 * i + 1];
        const float c  = conics[3 * i + 2];
        const float op = opac[i];

        // alpha = op*exp(-sigma) >= 1/255  <=>  sigma <= ln(255*op) = smax
        const float smax = logf(op * 255.0f);
        const float det  = a * c - b * b;

        d_A[r] = make_float4(mx, my, 0.5f * a, b);
        d_B[r] = make_float4(0.5f * c, smax, op, colors[3 * i]);
        d_C[r] = make_float2(colors[3 * i + 1], colors[3 * i + 2]);

        float4 bb;
        if (smax > 0.0f && det > 0.0f) {
            const float rx = sqrtf(fmaxf(0.0f, 2.0f * smax * c / det)) * 1.001f + 0.01f;
            const float ry = sqrtf(fmaxf(0.0f, 2.0f * smax * a / det)) * 1.001f + 0.01f;
            bb = make_float4(mx - rx, my - ry, mx + rx, my + ry);
        } else {
            bb = make_float4(1e9f, 1e9f, -1e9f, -1e9f);
        }
        d_bbox[r] = bb;
    }
}

// ---------------------------------------------------------------------------
// Exact (conservative) ellipse-vs-rect: keep iff min over rect of
// sigma(p) = A2*dx^2 + b*dx*dy + C2*dy^2 is <= smax (+margin).
// ---------------------------------------------------------------------------
__device__ __forceinline__ bool ellipse_hits_rect(
    float mx, float my, float A2, float b, float C2, float smax,
    float X0, float X1, float Y0, float Y1)
{
    if (mx >= X0 && mx <= X1 && my >= Y0 && my <= Y1) return true;
    const float dx0 = X0 - mx, dx1 = X1 - mx;
    const float dy0 = Y0 - my, dy1 = Y1 - my;
    const float fy = __fdividef(-b, 2.0f * C2);
    const float fx = __fdividef(-b, 2.0f * A2);

    float q = 3.4e38f;
    {   const float y = fminf(fmaxf(fy * dx0, dy0), dy1);
        q = fminf(q, A2 * dx0 * dx0 + b * dx0 * y + C2 * y * y); }
    {   const float y = fminf(fmaxf(fy * dx1, dy0), dy1);
        q = fminf(q, A2 * dx1 * dx1 + b * dx1 * y + C2 * y * y); }
    {   const float x = fminf(fmaxf(fx * dy0, dx0), dx1);
        q = fminf(q, A2 * x * x + b * x * dy0 + C2 * dy0 * dy0); }
    {   const float x = fminf(fmaxf(fx * dy1, dx0), dx1);
        q = fminf(q, A2 * x * x + b * x * dy1 + C2 * dy1 * dy1); }
    return q <= smax + 1e-2f;    // conservative margin (over-keep only)
}

// ---------------------------------------------------------------------------
// Kernel 2: binning. 8 lanes per gaussian (4 gaussians/warp); lanes split the
// covered tile range. atomicOr is order-independent -> deterministic.
// ---------------------------------------------------------------------------
__global__ __launch_bounds__(TPB) void binning_kernel()
{
    const int r   = (blockIdx.x * (TPB / 32) + (threadIdx.x >> 5)) * 4
                  + ((threadIdx.x >> 3) & 3);
    const int sub = threadIdx.x & 7;

    const float4 bb = d_bbox[r];
    if (bb.x > bb.z) return;

    const int tx0 = max(0, __float2int_rd((bb.x - 0.5f) * (1.0f / 16.0f)));
    const int tx1 = min(TX_N - 1, __float2int_rd((bb.z - 0.5f) * (1.0f / 16.0f)));
    const int ty0 = max(0, __float2int_rd((bb.y - 0.5f) * (1.0f / 16.0f)));
    const int ty1 = min(TY_N - 1, __float2int_rd((bb.w - 0.5f) * (1.0f / 16.0f)));
    if (tx1 < tx0 || ty1 < ty0) return;

    const int W = tx1 - tx0 + 1;
    const int n = W * (ty1 - ty0 + 1);

    const float4 A = d_A[r];    // mx, my, a/2, b
    const float4 B = d_B[r];    // c/2, smax, op, col.r

    for (int t = sub; t < n; t += 8) {
        const int tx = tx0 + t % W;
        const int ty = ty0 + t / W;
        const float X0 = (float)(tx * TILE) + 0.5f;
        const float Y0 = (float)(ty * TILE) + 0.5f;
        if (ellipse_hits_rect(A.x, A.y, A.z, A.w, B.x, B.y,
                              X0, X0 + (float)(TILE - 1),
                              Y0, Y0 + (float)(TILE - 1))) {
            const int tile = ty * TX_N + tx;
            atomicOr(&d_bits[tile * NWORDS + (r >> 5)], 1u << (r & 31));
        }
    }
}

// ---------------------------------------------------------------------------
// Kernel 3: raster. One 16x16 tile per block, 1 px/thread.
// Phase 1: bitmap -> compact uint16 rank list (ascending rank == depth order).
// Phase 2: per 512-entry chunk, cooperatively stage gaussian data into smem,
// then composite from smem (conflict-free broadcast LDS). All threads run the
// inner loop (per-thread work guarded by !done), so __all_sync sees the full
// warp; warp breaks when all 32 pixels reach T < 1e-4 (exact).
// ---------------------------------------------------------------------------
__global__ __launch_bounds__(TPB) void raster_kernel(float* __restrict__ out)
{
    const int tileX = blockIdx.x, tileY = blockIdx.y;
    const int tileI = tileY * TX_N + tileX;
    const int tid   = threadIdx.x;
    const int warp  = tid >> 5, lane = tid & 31;
    const float px  = (float)(tileX * TILE + (tid & (TILE - 1))) + 0.5f;
    const float py  = (float)(tileY * TILE + (tid >> 4)) + 0.5f;

    __shared__ unsigned short s_list[G_N];   // 16 KB
    __shared__ float4 s_A[CH];               // 8 KB
    __shared__ float4 s_B[CH];               // 8 KB
    __shared__ float2 s_C[CH];               // 4 KB
    __shared__ int s_wsum[8];
    __shared__ int s_cnt;

    // ---- Phase 1: build list ----
    const unsigned w = d_bits[tileI * NWORDS + tid];
    const int c = __popc(w);

    int incl = c;
#pragma unroll
    for (int o = 1; o < 32; o <<= 1) {
        const int v = __shfl_up_sync(0xffffffffu, incl, o);
        if (lane >= o) incl += v;
    }
    if (lane == 31) s_wsum[warp] = incl;
    __syncthreads();
    int base = 0;
#pragma unroll
    for (int k = 0; k < 8; ++k)
        if (k < warp) base += s_wsum[k];
    if (tid == 0) {
        int tot = 0;
#pragma unroll
        for (int k = 0; k < 8; ++k) tot += s_wsum[k];
        s_cnt = tot;
    }
    int ofs = base + incl - c;
    unsigned bits = w;
    const int rbase = tid << 5;
    while (bits) {
        const int rb = __ffs(bits) - 1;
        bits &= bits - 1;
        s_list[ofs++] = (unsigned short)(rbase + rb);
    }
    __syncthreads();
    const int cnt = s_cnt;

    // ---- Phase 2: chunked stage + composite ----
    float T = 1.0f;
    float aR = 0.0f, aG = 0.0f, aB = 0.0f;
    bool done = false;

    for (int c0 = 0; c0 < cnt; c0 += CH) {
        const int n = min(CH, cnt - c0);
        // stage this chunk (all threads participate; typical cnt <= CH)
        for (int k = tid; k < n; k += TPB) {
            const int r = s_list[c0 + k];
            s_A[k] = d_A[r];
            s_B[k] = d_B[r];
            s_C[k] = d_C[r];
        }
        __syncthreads();

        // all threads execute the loop; __all_sync sees the full warp
#pragma unroll 1
        for (int j = 0; j < n; ++j) {
            if (!done) {
                const float4 A = s_A[j];       // broadcast LDS
                const float4 B = s_B[j];
                const float dx = px - A.x;
                const float dy = py - A.y;
                const float sg = fmaf(A.z * dx, dx,
                                 fmaf(B.x * dy, dy, A.w * dx * dy));
                if (sg >= 0.0f && sg <= B.y) {
                    const float2 C = s_C[j];
                    const float alpha = fminf(0.99f, B.z * __expf(-sg));
                    const float wgt = alpha * T;
                    aR += wgt * B.w; aG += wgt * C.x; aB += wgt * C.y;
                    T *= (1.0f - alpha);
                    done = (T < 1e-4f);
                }
            }
            if (__all_sync(0xffffffffu, done)) break;
        }
        __syncthreads();   // chunk consumed before restaging
    }

    float* o = out + ((size_t)(tileY * TILE + (tid >> 4)) * IMG_W
                      + (tileX * TILE + (tid & (TILE - 1)))) * 3;
    o[0] = aR;
    o[1] = aG;
    o[2] = aB;
}

// ---------------------------------------------------------------------------
extern "C" void kernel_launch(void* const* d_in, const int* in_sizes, int n_in,
                              void* d_out, int out_size)
{
    const float* means2d   = (const float*)d_in[0];
    const float* conics    = (const float*)d_in[1];
    const float* colors    = (const float*)d_in[2];
    const float* opacities = (const float*)d_in[3];
    const float* depths    = (const float*)d_in[4];
    float* out = (float*)d_out;

    sort_gather_kernel<<<SORT_BLOCKS, SORT_TPB>>>(means2d, conics, colors, opacities, depths);
    binning_kernel<<<G_N / ((TPB / 32) * 4), TPB>>>();
    dim3 grid(TX_N, TY_N);
    raster_kernel<<<grid, TPB>>>(out);
}